// round 3
// baseline (speedup 1.0000x reference)
#include <cuda_runtime.h>
#include <math.h>

#define BB 4
#define TT 4096
#define EE 256
#define AA 64
#define MTOT (BB*TT)   // 16384

// Scratch for projected q/k/v (device globals: no allocation allowed)
__device__ float g_q[BB*TT*AA];
__device__ float g_k[BB*TT*AA];
__device__ float g_v[BB*TT*AA];

// ---------------------------------------------------------------------------
// Projection: C[m, a] = X[m, :] @ W[:, a] + b[a]   (scale folded into Q)
// grid = (MTOT/64, 3), block = 256 threads, 64x64 tiles, 4x4 register tiles.
// ---------------------------------------------------------------------------
__global__ __launch_bounds__(256) void proj_kernel(
    const float* __restrict__ X,
    const float* __restrict__ Wk, const float* __restrict__ bk,
    const float* __restrict__ Wq, const float* __restrict__ bq,
    const float* __restrict__ Wv, const float* __restrict__ bv)
{
    __shared__ float Xs[64][68];  // transposed: Xs[e][i], pad for f4 alignment
    __shared__ float Ws[64][68];  // Ws[e][n]

    const float* W; const float* bias; float* outp; float scl;
    if (blockIdx.y == 0)      { W = Wq; bias = bq; outp = g_q; scl = 0.125f; }
    else if (blockIdx.y == 1) { W = Wk; bias = bk; outp = g_k; scl = 1.0f; }
    else                      { W = Wv; bias = bv; outp = g_v; scl = 1.0f; }

    const int t  = threadIdx.x;
    const int tx = t & 15;
    const int ty = t >> 4;
    const int m0 = blockIdx.x * 64;

    float acc[4][4];
#pragma unroll
    for (int r = 0; r < 4; r++)
#pragma unroll
        for (int c = 0; c < 4; c++) acc[r][c] = 0.f;

    for (int e0 = 0; e0 < EE; e0 += 64) {
#pragma unroll
        for (int rep = 0; rep < 16; rep++) {
            int idx = t + rep * 256;
            int i = idx >> 6;
            int j = idx & 63;
            Xs[j][i] = X[(m0 + i) * EE + e0 + j];   // transpose on store
            Ws[i][j] = W[(e0 + i) * AA + j];
        }
        __syncthreads();
#pragma unroll 8
        for (int e = 0; e < 64; e++) {
            float4 xa = *(const float4*)&Xs[e][ty * 4];
            float4 wb = *(const float4*)&Ws[e][tx * 4];
            acc[0][0] += xa.x * wb.x; acc[0][1] += xa.x * wb.y; acc[0][2] += xa.x * wb.z; acc[0][3] += xa.x * wb.w;
            acc[1][0] += xa.y * wb.x; acc[1][1] += xa.y * wb.y; acc[1][2] += xa.y * wb.z; acc[1][3] += xa.y * wb.w;
            acc[2][0] += xa.z * wb.x; acc[2][1] += xa.z * wb.y; acc[2][2] += xa.z * wb.z; acc[2][3] += xa.z * wb.w;
            acc[3][0] += xa.w * wb.x; acc[3][1] += xa.w * wb.y; acc[3][2] += xa.w * wb.z; acc[3][3] += xa.w * wb.w;
        }
        __syncthreads();
    }

#pragma unroll
    for (int r = 0; r < 4; r++) {
#pragma unroll
        for (int c = 0; c < 4; c++) {
            int n = tx * 4 + c;
            outp[(m0 + ty * 4 + r) * AA + n] = (acc[r][c] + bias[n]) * scl;
        }
    }
}

// ---------------------------------------------------------------------------
// Flash attention (causal), fp32, BQ = BK = 64, D = 64.
// grid = (TT/64, BB), block = 256 threads.
// ---------------------------------------------------------------------------
__global__ __launch_bounds__(256) void flash_kernel(float* __restrict__ out)
{
    extern __shared__ float sm[];
    float* Qt   = sm;               // [64][68] d-major: Qt[d][i]
    float* Kt   = Qt + 64 * 68;     // [64][68] d-major: Kt[d][j]
    float* Vs   = Kt + 64 * 68;     // [64][68] row-major: Vs[j][d]
    float* Ss   = Vs + 64 * 68;     // [64][68] scores / probs
    float* rowm = Ss + 64 * 68;     // [64]
    float* rowl = rowm + 64;        // [64]
    float* rowc = rowl + 64;        // [64]

    const int t  = threadIdx.x;
    const int tx = t & 15;
    const int ty = t >> 4;
    const int qt = blockIdx.x;
    const int b  = blockIdx.y;

    const float* qp    = g_q + (b * TT + qt * 64) * AA;
    const float* kbase = g_k + b * TT * AA;
    const float* vbase = g_v + b * TT * AA;

#pragma unroll
    for (int rep = 0; rep < 16; rep++) {
        int idx = t + rep * 256;
        int i = idx >> 6;
        int a = idx & 63;
        Qt[a * 68 + i] = qp[i * AA + a];
    }
    if (t < 64) { rowm[t] = -INFINITY; rowl[t] = 0.f; }

    float O[4][4];
#pragma unroll
    for (int r = 0; r < 4; r++)
#pragma unroll
        for (int c = 0; c < 4; c++) O[r][c] = 0.f;

    __syncthreads();

    for (int kt = 0; kt <= qt; kt++) {
        const float* kp = kbase + kt * 64 * AA;
        const float* vp = vbase + kt * 64 * AA;
#pragma unroll
        for (int rep = 0; rep < 16; rep++) {
            int idx = t + rep * 256;
            int i = idx >> 6;
            int a = idx & 63;
            Kt[a * 68 + i] = kp[i * AA + a];
            Vs[i * 68 + a] = vp[i * AA + a];
        }
        __syncthreads();

        // ---- S = Q @ K^T (scale already folded into Q) ----
        float s[4][4];
#pragma unroll
        for (int r = 0; r < 4; r++)
#pragma unroll
            for (int c = 0; c < 4; c++) s[r][c] = 0.f;

#pragma unroll 8
        for (int d = 0; d < 64; d++) {
            float4 qa = *(const float4*)&Qt[d * 68 + ty * 4];
            float4 kb = *(const float4*)&Kt[d * 68 + tx * 4];
            s[0][0] += qa.x * kb.x; s[0][1] += qa.x * kb.y; s[0][2] += qa.x * kb.z; s[0][3] += qa.x * kb.w;
            s[1][0] += qa.y * kb.x; s[1][1] += qa.y * kb.y; s[1][2] += qa.y * kb.z; s[1][3] += qa.y * kb.w;
            s[2][0] += qa.z * kb.x; s[2][1] += qa.z * kb.y; s[2][2] += qa.z * kb.z; s[2][3] += qa.z * kb.w;
            s[3][0] += qa.w * kb.x; s[3][1] += qa.w * kb.y; s[3][2] += qa.w * kb.z; s[3][3] += qa.w * kb.w;
        }

        // Causal mask (only needed on the diagonal tile; tiles are aligned)
        if (kt == qt) {
#pragma unroll
            for (int r = 0; r < 4; r++)
#pragma unroll
                for (int c = 0; c < 4; c++)
                    if (tx * 4 + c > ty * 4 + r) s[r][c] = -INFINITY;
        }

#pragma unroll
        for (int r = 0; r < 4; r++)
#pragma unroll
            for (int c = 0; c < 4; c++)
                Ss[(ty * 4 + r) * 68 + tx * 4 + c] = s[r][c];
        __syncthreads();

        // ---- online softmax row pass: one thread per q row ----
        if (t < 64) {
            float* srow = Ss + t * 68;
            float mo = rowm[t];
            float mx = mo;
#pragma unroll 8
            for (int j = 0; j < 64; j++) mx = fmaxf(mx, srow[j]);
            float corr = __expf(mo - mx);   // mo=-inf -> 0 (mx finite: diag always valid)
            float sum = 0.f;
#pragma unroll 8
            for (int j = 0; j < 64; j++) {
                float p = __expf(srow[j] - mx);
                srow[j] = p;
                sum += p;
            }
            rowl[t] = rowl[t] * corr + sum;
            rowm[t] = mx;
            rowc[t] = corr;
        }
        __syncthreads();

        // ---- O = O * corr + P @ V ----
        float cr[4];
#pragma unroll
        for (int r = 0; r < 4; r++) cr[r] = rowc[ty * 4 + r];
#pragma unroll
        for (int r = 0; r < 4; r++)
#pragma unroll
            for (int c = 0; c < 4; c++) O[r][c] *= cr[r];

#pragma unroll 8
        for (int j = 0; j < 64; j++) {
            float4 vb = *(const float4*)&Vs[j * 68 + tx * 4];
            float p0 = Ss[(ty * 4 + 0) * 68 + j];
            float p1 = Ss[(ty * 4 + 1) * 68 + j];
            float p2 = Ss[(ty * 4 + 2) * 68 + j];
            float p3 = Ss[(ty * 4 + 3) * 68 + j];
            O[0][0] += p0 * vb.x; O[0][1] += p0 * vb.y; O[0][2] += p0 * vb.z; O[0][3] += p0 * vb.w;
            O[1][0] += p1 * vb.x; O[1][1] += p1 * vb.y; O[1][2] += p1 * vb.z; O[1][3] += p1 * vb.w;
            O[2][0] += p2 * vb.x; O[2][1] += p2 * vb.y; O[2][2] += p2 * vb.z; O[2][3] += p2 * vb.w;
            O[3][0] += p3 * vb.x; O[3][1] += p3 * vb.y; O[3][2] += p3 * vb.z; O[3][3] += p3 * vb.w;
        }
        __syncthreads();
    }

    // ---- epilogue: divide by l ----
    float inv[4];
#pragma unroll
    for (int r = 0; r < 4; r++) inv[r] = 1.0f / rowl[ty * 4 + r];

#pragma unroll
    for (int r = 0; r < 4; r++) {
#pragma unroll
        for (int c = 0; c < 4; c++) {
            out[(b * TT + qt * 64 + ty * 4 + r) * AA + tx * 4 + c] = O[r][c] * inv[r];
        }
    }
}

static const int FLASH_SMEM = (4 * 64 * 68 + 3 * 64) * (int)sizeof(float);  // 70400

extern "C" void kernel_launch(void* const* d_in, const int* in_sizes, int n_in,
                              void* d_out, int out_size)
{
    const float* X  = (const float*)d_in[0];
    const float* Wk = (const float*)d_in[1];
    const float* bk = (const float*)d_in[2];
    const float* Wq = (const float*)d_in[3];
    const float* bq = (const float*)d_in[4];
    const float* Wv = (const float*)d_in[5];
    const float* bv = (const float*)d_in[6];
    float* out = (float*)d_out;

    cudaFuncSetAttribute(flash_kernel, cudaFuncAttributeMaxDynamicSharedMemorySize, FLASH_SMEM);

    dim3 pg(MTOT / 64, 3);
    proj_kernel<<<pg, 256>>>(X, Wk, bk, Wq, bq, Wv, bv);

    dim3 fg(TT / 64, BB);
    flash_kernel<<<fg, 256, FLASH_SMEM>>>(out);
}

// round 4
// speedup vs baseline: 1.0067x; 1.0067x over previous
#include <cuda_runtime.h>
#include <math.h>

#define BB 4
#define TT 4096
#define EE 256
#define AA 64
#define MTOT (BB*TT)   // 16384

// Scratch for projected q/k/v (device globals: no allocation allowed)
__device__ float g_q[BB*TT*AA];
__device__ float g_k[BB*TT*AA];
__device__ float g_v[BB*TT*AA];

// ---------------------------------------------------------------------------
// Projection: C[m, a] = X[m, :] @ W[:, a] + b[a]   (scale folded into Q)
// grid = (MTOT/64, 3), block = 256 threads, 64x64 tiles, 4x4 register tiles.
// ---------------------------------------------------------------------------
__global__ __launch_bounds__(256) void proj_kernel(
    const float* __restrict__ X,
    const float* __restrict__ Wk, const float* __restrict__ bk,
    const float* __restrict__ Wq, const float* __restrict__ bq,
    const float* __restrict__ Wv, const float* __restrict__ bv)
{
    __shared__ float Xs[64][68];  // transposed: Xs[e][i], pad for f4 alignment
    __shared__ float Ws[64][68];  // Ws[e][n]

    const float* W; const float* bias; float* outp; float scl;
    if (blockIdx.y == 0)      { W = Wq; bias = bq; outp = g_q; scl = 0.125f; }
    else if (blockIdx.y == 1) { W = Wk; bias = bk; outp = g_k; scl = 1.0f; }
    else                      { W = Wv; bias = bv; outp = g_v; scl = 1.0f; }

    const int t  = threadIdx.x;
    const int tx = t & 15;
    const int ty = t >> 4;
    const int m0 = blockIdx.x * 64;

    float acc[4][4];
#pragma unroll
    for (int r = 0; r < 4; r++)
#pragma unroll
        for (int c = 0; c < 4; c++) acc[r][c] = 0.f;

    for (int e0 = 0; e0 < EE; e0 += 64) {
#pragma unroll
        for (int rep = 0; rep < 16; rep++) {
            int idx = t + rep * 256;
            int i = idx >> 6;
            int j = idx & 63;
            Xs[j][i] = X[(m0 + i) * EE + e0 + j];   // transpose on store
            Ws[i][j] = W[(e0 + i) * AA + j];
        }
        __syncthreads();
#pragma unroll 8
        for (int e = 0; e < 64; e++) {
            float4 xa = *(const float4*)&Xs[e][ty * 4];
            float4 wb = *(const float4*)&Ws[e][tx * 4];
            acc[0][0] += xa.x * wb.x; acc[0][1] += xa.x * wb.y; acc[0][2] += xa.x * wb.z; acc[0][3] += xa.x * wb.w;
            acc[1][0] += xa.y * wb.x; acc[1][1] += xa.y * wb.y; acc[1][2] += xa.y * wb.z; acc[1][3] += xa.y * wb.w;
            acc[2][0] += xa.z * wb.x; acc[2][1] += xa.z * wb.y; acc[2][2] += xa.z * wb.z; acc[2][3] += xa.z * wb.w;
            acc[3][0] += xa.w * wb.x; acc[3][1] += xa.w * wb.y; acc[3][2] += xa.w * wb.z; acc[3][3] += xa.w * wb.w;
        }
        __syncthreads();
    }

#pragma unroll
    for (int r = 0; r < 4; r++) {
#pragma unroll
        for (int c = 0; c < 4; c++) {
            int n = tx * 4 + c;
            outp[(m0 + ty * 4 + r) * AA + n] = (acc[r][c] + bias[n]) * scl;
        }
    }
}

// ---------------------------------------------------------------------------
// Flash attention (causal), fp32, BQ = BK = 64, D = 64.
// grid = (TT/64, BB), block = 256 threads.
// ---------------------------------------------------------------------------
__global__ __launch_bounds__(256) void flash_kernel(float* __restrict__ out)
{
    extern __shared__ float sm[];
    float* Qt   = sm;               // [64][68] d-major: Qt[d][i]
    float* Kt   = Qt + 64 * 68;     // [64][68] d-major: Kt[d][j]
    float* Vs   = Kt + 64 * 68;     // [64][68] row-major: Vs[j][d]
    float* Ss   = Vs + 64 * 68;     // [64][68] scores / probs
    float* rowm = Ss + 64 * 68;     // [64]
    float* rowl = rowm + 64;        // [64]
    float* rowc = rowl + 64;        // [64]

    const int t  = threadIdx.x;
    const int tx = t & 15;
    const int ty = t >> 4;
    const int qt = blockIdx.x;
    const int b  = blockIdx.y;

    const float* qp    = g_q + (b * TT + qt * 64) * AA;
    const float* kbase = g_k + b * TT * AA;
    const float* vbase = g_v + b * TT * AA;

#pragma unroll
    for (int rep = 0; rep < 16; rep++) {
        int idx = t + rep * 256;
        int i = idx >> 6;
        int a = idx & 63;
        Qt[a * 68 + i] = qp[i * AA + a];
    }
    if (t < 64) { rowm[t] = -INFINITY; rowl[t] = 0.f; }

    float O[4][4];
#pragma unroll
    for (int r = 0; r < 4; r++)
#pragma unroll
        for (int c = 0; c < 4; c++) O[r][c] = 0.f;

    __syncthreads();

    for (int kt = 0; kt <= qt; kt++) {
        const float* kp = kbase + kt * 64 * AA;
        const float* vp = vbase + kt * 64 * AA;
#pragma unroll
        for (int rep = 0; rep < 16; rep++) {
            int idx = t + rep * 256;
            int i = idx >> 6;
            int a = idx & 63;
            Kt[a * 68 + i] = kp[i * AA + a];
            Vs[i * 68 + a] = vp[i * AA + a];
        }
        __syncthreads();

        // ---- S = Q @ K^T (scale already folded into Q) ----
        float s[4][4];
#pragma unroll
        for (int r = 0; r < 4; r++)
#pragma unroll
            for (int c = 0; c < 4; c++) s[r][c] = 0.f;

#pragma unroll 8
        for (int d = 0; d < 64; d++) {
            float4 qa = *(const float4*)&Qt[d * 68 + ty * 4];
            float4 kb = *(const float4*)&Kt[d * 68 + tx * 4];
            s[0][0] += qa.x * kb.x; s[0][1] += qa.x * kb.y; s[0][2] += qa.x * kb.z; s[0][3] += qa.x * kb.w;
            s[1][0] += qa.y * kb.x; s[1][1] += qa.y * kb.y; s[1][2] += qa.y * kb.z; s[1][3] += qa.y * kb.w;
            s[2][0] += qa.z * kb.x; s[2][1] += qa.z * kb.y; s[2][2] += qa.z * kb.z; s[2][3] += qa.z * kb.w;
            s[3][0] += qa.w * kb.x; s[3][1] += qa.w * kb.y; s[3][2] += qa.w * kb.z; s[3][3] += qa.w * kb.w;
        }

        // Causal mask (only needed on the diagonal tile; tiles are aligned)
        if (kt == qt) {
#pragma unroll
            for (int r = 0; r < 4; r++)
#pragma unroll
                for (int c = 0; c < 4; c++)
                    if (tx * 4 + c > ty * 4 + r) s[r][c] = -INFINITY;
        }

#pragma unroll
        for (int r = 0; r < 4; r++)
#pragma unroll
            for (int c = 0; c < 4; c++)
                Ss[(ty * 4 + r) * 68 + tx * 4 + c] = s[r][c];
        __syncthreads();

        // ---- online softmax row pass: one thread per q row ----
        if (t < 64) {
            float* srow = Ss + t * 68;
            float mo = rowm[t];
            float mx = mo;
#pragma unroll 8
            for (int j = 0; j < 64; j++) mx = fmaxf(mx, srow[j]);
            float corr = __expf(mo - mx);   // mo=-inf -> 0 (mx finite: diag always valid)
            float sum = 0.f;
#pragma unroll 8
            for (int j = 0; j < 64; j++) {
                float p = __expf(srow[j] - mx);
                srow[j] = p;
                sum += p;
            }
            rowl[t] = rowl[t] * corr + sum;
            rowm[t] = mx;
            rowc[t] = corr;
        }
        __syncthreads();

        // ---- O = O * corr + P @ V ----
        float cr[4];
#pragma unroll
        for (int r = 0; r < 4; r++) cr[r] = rowc[ty * 4 + r];
#pragma unroll
        for (int r = 0; r < 4; r++)
#pragma unroll
            for (int c = 0; c < 4; c++) O[r][c] *= cr[r];

#pragma unroll 8
        for (int j = 0; j < 64; j++) {
            float4 vb = *(const float4*)&Vs[j * 68 + tx * 4];
            float p0 = Ss[(ty * 4 + 0) * 68 + j];
            float p1 = Ss[(ty * 4 + 1) * 68 + j];
            float p2 = Ss[(ty * 4 + 2) * 68 + j];
            float p3 = Ss[(ty * 4 + 3) * 68 + j];
            O[0][0] += p0 * vb.x; O[0][1] += p0 * vb.y; O[0][2] += p0 * vb.z; O[0][3] += p0 * vb.w;
            O[1][0] += p1 * vb.x; O[1][1] += p1 * vb.y; O[1][2] += p1 * vb.z; O[1][3] += p1 * vb.w;
            O[2][0] += p2 * vb.x; O[2][1] += p2 * vb.y; O[2][2] += p2 * vb.z; O[2][3] += p2 * vb.w;
            O[3][0] += p3 * vb.x; O[3][1] += p3 * vb.y; O[3][2] += p3 * vb.z; O[3][3] += p3 * vb.w;
        }
        __syncthreads();
    }

    // ---- epilogue: divide by l ----
    float inv[4];
#pragma unroll
    for (int r = 0; r < 4; r++) inv[r] = 1.0f / rowl[ty * 4 + r];

#pragma unroll
    for (int r = 0; r < 4; r++) {
#pragma unroll
        for (int c = 0; c < 4; c++) {
            out[(b * TT + qt * 64 + ty * 4 + r) * AA + tx * 4 + c] = O[r][c] * inv[r];
        }
    }
}

static const int FLASH_SMEM = (4 * 64 * 68 + 3 * 64) * (int)sizeof(float);  // 70400

extern "C" void kernel_launch(void* const* d_in, const int* in_sizes, int n_in,
                              void* d_out, int out_size)
{
    const float* X  = (const float*)d_in[0];
    const float* Wk = (const float*)d_in[1];
    const float* bk = (const float*)d_in[2];
    const float* Wq = (const float*)d_in[3];
    const float* bq = (const float*)d_in[4];
    const float* Wv = (const float*)d_in[5];
    const float* bv = (const float*)d_in[6];
    float* out = (float*)d_out;

    cudaFuncSetAttribute(flash_kernel, cudaFuncAttributeMaxDynamicSharedMemorySize, FLASH_SMEM);

    dim3 pg(MTOT / 64, 3);
    proj_kernel<<<pg, 256>>>(X, Wk, bk, Wq, bq, Wv, bv);

    dim3 fg(TT / 64, BB);
    flash_kernel<<<fg, 256, FLASH_SMEM>>>(out);
}